// round 11
// baseline (speedup 1.0000x reference)
#include <cuda_runtime.h>
#include <cuda_fp16.h>
#include <math.h>
#include <stdint.h>

#define NDIM 4096
#define DDIM 1024
#define HSZ ((size_t)NDIM * DDIM)
#define NN  ((size_t)NDIM * NDIM)

// ---------------- scratch (device globals) ----------------
__device__ __half g_Sh[3 * NN];
__device__ __half g_Hh[3 * HSZ];
__device__ __half g_HT[3 * HSZ];
__device__ __half g_H4[(size_t)NDIM * 3 * DDIM];
__device__ __half g_Wh[(size_t)DDIM * 3 * DDIM];
__device__ unsigned char g_MT[NN];

// dataflow state (zero-init; reset by last CTA each run)
__device__ unsigned g_tickA, g_tickB, g_tickC, g_tickD, g_done;
__device__ unsigned g_cntS[96];   // score tiles done per (z,mblock): 32 each
__device__ unsigned g_cntP[96];   // softmax chunks done per (z,mblock): 16 each
__device__ unsigned g_cntH[32];   // AV tiles done per mblock: 24 each

// ---------------- PTX helpers ----------------
__device__ __forceinline__ uint32_t smem_u32(const void* p) {
    uint32_t a;
    asm("{ .reg .u64 t; cvta.to.shared.u64 t, %1; cvt.u32.u64 %0, t; }" : "=r"(a) : "l"(p));
    return a;
}
__device__ __forceinline__ void cp_async16(uint32_t dst, const void* src) {
    asm volatile("cp.async.cg.shared.global [%0], [%1], 16;" :: "r"(dst), "l"(src) : "memory");
}
__device__ __forceinline__ void cp_commit() {
    asm volatile("cp.async.commit_group;" ::: "memory");
}
template <int N>
__device__ __forceinline__ void cp_wait() {
    asm volatile("cp.async.wait_group %0;" :: "n"(N) : "memory");
}
__device__ __forceinline__ void ldsm4(uint32_t* d, uint32_t addr) {
    asm volatile("ldmatrix.sync.aligned.m8n8.x4.shared.b16 {%0,%1,%2,%3}, [%4];"
        : "=r"(d[0]), "=r"(d[1]), "=r"(d[2]), "=r"(d[3]) : "r"(addr));
}
__device__ __forceinline__ void mma_f32(float* c, const uint32_t* a, const uint32_t* b) {
    asm volatile("mma.sync.aligned.m16n8k16.row.col.f32.f16.f16.f32 "
        "{%0,%1,%2,%3}, {%4,%5,%6,%7}, {%8,%9}, {%0,%1,%2,%3};"
        : "+f"(c[0]), "+f"(c[1]), "+f"(c[2]), "+f"(c[3])
        : "r"(a[0]), "r"(a[1]), "r"(a[2]), "r"(a[3]), "r"(b[0]), "r"(b[1]));
}
__device__ __forceinline__ void mma_f16acc(uint32_t* c, const uint32_t* a, const uint32_t* b) {
    asm volatile("mma.sync.aligned.m16n8k16.row.col.f16.f16.f16.f16 "
        "{%0,%1}, {%2,%3,%4,%5}, {%6,%7}, {%0,%1};"
        : "+r"(c[0]), "+r"(c[1])
        : "r"(a[0]), "r"(a[1]), "r"(a[2]), "r"(a[3]), "r"(b[0]), "r"(b[1]));
}

__device__ __forceinline__ uint32_t soff64(int r, int c) {
    return (uint32_t)(r * 64 + ((c ^ ((r >> 1) & 3)) << 4));
}

#define OPB (128 * 64)
#define STB (2 * OPB)
#define NST 3
#define BKE 32

// ============================================================================
// one GEMM tile (NT). MODE 0: f16 accum -> *alpha -> half (scores)
//                     MODE 1: f32 accum -> half (AV)
//                     MODE 2: f32 accum -> tanh(+bias) -> float (final)
// BN = 128 or 64.  Ends fully drained (cp.async + barrier).
// ============================================================================
template <int MODE, int BN>
__device__ void gemm_tile(char* sm, const int t,
    const __half* __restrict__ A, const int lda,
    const __half* __restrict__ B, const int ldb, const int K,
    const float alpha, __half* __restrict__ Ch, float* __restrict__ Cf,
    const int ldc, const float* __restrict__ bias, const int m0, const int n0)
{
    constexpr int WN = BN / 2;
    constexpr int NJ = WN / 8;
    constexpr int NB = WN / 16;
    const int lane = t & 31;
    const int wid  = t >> 5;
    const int wm   = (wid & 3) * 32;
    const int wn   = (wid >> 2) * WN;
    const uint32_t sbase = smem_u32(sm);

    const int rl = t >> 2;
    const int cl = t & 3;
    const uint32_t st0 = soff64(rl, cl);
    const uint32_t st1 = soff64(rl + 64, cl);
    const __half* gA0 = A + (size_t)(m0 + rl) * lda + cl * 8;
    const __half* gA1 = A + (size_t)(m0 + rl + 64) * lda + cl * 8;
    const __half* gB0 = B + (size_t)(n0 + rl) * ldb + cl * 8;
    const __half* gB1 = (BN == 128) ? (B + (size_t)(n0 + rl + 64) * ldb + cl * 8) : gB0;

    uint32_t adA[2][2], adB[2][NB];
    {
        const int mm = lane >> 3;
#pragma unroll
        for (int ks = 0; ks < 2; ks++) {
#pragma unroll
            for (int i = 0; i < 2; i++)
                adA[ks][i] = soff64(wm + i * 16 + (mm & 1) * 8 + (lane & 7), 2 * ks + (mm >> 1));
#pragma unroll
            for (int j = 0; j < NB; j++)
                adB[ks][j] = soff64(wn + j * 16 + (mm >> 1) * 8 + (lane & 7), 2 * ks + (mm & 1));
        }
    }

    float    accf[2][NJ][4];
    uint32_t acch[2][NJ][2];
#pragma unroll
    for (int i = 0; i < 2; i++)
#pragma unroll
        for (int j = 0; j < NJ; j++) {
            if (MODE == 0) { acch[i][j][0] = 0u; acch[i][j][1] = 0u; }
            else {
#pragma unroll
                for (int q = 0; q < 4; q++) accf[i][j][q] = 0.f;
            }
        }

    const int T = K / BKE;
#pragma unroll
    for (int s = 0; s < NST - 1; s++) {
        const uint32_t d = sbase + s * STB;
        const int k = s * BKE;
        cp_async16(d + st0, gA0 + k);
        cp_async16(d + st1, gA1 + k);
        cp_async16(d + OPB + st0, gB0 + k);
        if (BN == 128) cp_async16(d + OPB + st1, gB1 + k);
        cp_commit();
    }
    for (int tt = 0; tt < T; tt++) {
        __syncthreads();
        const int nt = tt + NST - 1;
        if (nt < T) {
            const uint32_t d = sbase + (nt % NST) * STB;
            const int k = nt * BKE;
            cp_async16(d + st0, gA0 + k);
            cp_async16(d + st1, gA1 + k);
            cp_async16(d + OPB + st0, gB0 + k);
            if (BN == 128) cp_async16(d + OPB + st1, gB1 + k);
        }
        cp_commit();
        cp_wait<NST - 2>();
        __syncthreads();

        const uint32_t sb = sbase + (tt % NST) * STB;
#pragma unroll
        for (int ks = 0; ks < 2; ks++) {
            uint32_t a[2][4], b[2 * NB][2];
            ldsm4(a[0], sb + adA[ks][0]);
            ldsm4(a[1], sb + adA[ks][1]);
#pragma unroll
            for (int j = 0; j < NB; j++) {
                uint32_t tmp[4];
                ldsm4(tmp, sb + OPB + adB[ks][j]);
                b[2*j][0]   = tmp[0]; b[2*j][1]   = tmp[1];
                b[2*j+1][0] = tmp[2]; b[2*j+1][1] = tmp[3];
            }
#pragma unroll
            for (int i = 0; i < 2; i++)
#pragma unroll
                for (int j = 0; j < NJ; j++) {
                    if (MODE == 0) mma_f16acc(acch[i][j], a[i], b[j]);
                    else           mma_f32(accf[i][j], a[i], b[j]);
                }
        }
    }
    cp_wait<0>();
    __syncthreads();

    const int row0 = m0 + wm + (lane >> 2);
    const int colb = n0 + wn + (lane & 3) * 2;
    if (MODE == 0) {
        const __half2 sc2 = __float2half2_rn(alpha);
#pragma unroll
        for (int i = 0; i < 2; i++)
#pragma unroll
            for (int j = 0; j < NJ; j++) {
                const int r0 = row0 + i * 16;
                const int col = colb + j * 8;
                *(__half2*)(Ch + (size_t)r0 * ldc + col)       = __hmul2(*(__half2*)&acch[i][j][0], sc2);
                *(__half2*)(Ch + (size_t)(r0 + 8) * ldc + col) = __hmul2(*(__half2*)&acch[i][j][1], sc2);
            }
    } else if (MODE == 1) {
#pragma unroll
        for (int i = 0; i < 2; i++)
#pragma unroll
            for (int j = 0; j < NJ; j++) {
                const int r0 = row0 + i * 16;
                const int col = colb + j * 8;
                const float* c = accf[i][j];
                __half2 v0; v0.x = __float2half_rn(c[0]); v0.y = __float2half_rn(c[1]);
                __half2 v1; v1.x = __float2half_rn(c[2]); v1.y = __float2half_rn(c[3]);
                *(__half2*)(Ch + (size_t)r0 * ldc + col)       = v0;
                *(__half2*)(Ch + (size_t)(r0 + 8) * ldc + col) = v1;
            }
    } else {
#pragma unroll
        for (int i = 0; i < 2; i++)
#pragma unroll
            for (int j = 0; j < NJ; j++) {
                const int r0 = row0 + i * 16;
                const int col = colb + j * 8;
                const float* c = accf[i][j];
                *(float2*)(Cf + (size_t)r0 * ldc + col) =
                    make_float2(tanhf(c[0] + bias[col]), tanhf(c[1] + bias[col + 1]));
                *(float2*)(Cf + (size_t)(r0 + 8) * ldc + col) =
                    make_float2(tanhf(c[2] + bias[col]), tanhf(c[3] + bias[col + 1]));
            }
    }
}

// ---------------- reductions + register-resident softmax row ----------------
__device__ __forceinline__ float warp_red_max(float v) {
#pragma unroll
    for (int o = 16; o; o >>= 1) v = fmaxf(v, __shfl_xor_sync(0xffffffffu, v, o));
    return v;
}
__device__ __forceinline__ float warp_red_sum(float v) {
#pragma unroll
    for (int o = 16; o; o >>= 1) v += __shfl_xor_sync(0xffffffffu, v, o);
    return v;
}
template <bool IS_MAX>
__device__ __forceinline__ float block_red(float v, float* red, int t) {
    v = IS_MAX ? warp_red_max(v) : warp_red_sum(v);
    __syncthreads();
    if ((t & 31) == 0) red[t >> 5] = v;
    __syncthreads();
    if (t < 32) {
        float x = (t < 8) ? red[t] : (IS_MAX ? -INFINITY : 0.f);
        x = IS_MAX ? warp_red_max(x) : warp_red_sum(x);
        if (t == 0) red[0] = x;
    }
    __syncthreads();
    return red[0];
}

__device__ void softmax_row(__half* __restrict__ Srow,
                            const float* __restrict__ mrowf,
                            const unsigned char* __restrict__ mrowb,
                            const int t, float* red)
{
    float r[16];
    float mx = -INFINITY;
#pragma unroll
    for (int c = 0; c < 2; c++) {
        uint4 raw = __ldcg((const uint4*)(Srow + c * 2048 + t * 8));
        const __half2* h2 = (const __half2*)&raw;
#pragma unroll
        for (int q = 0; q < 4; q++) {
            float2 f = __half22float2(h2[q]);
            r[c*8 + 2*q]     = f.x;
            r[c*8 + 2*q + 1] = f.y;
            mx = fmaxf(mx, fmaxf(f.x, f.y));
        }
    }
    const float smax = block_red<true>(mx, red, t);

    float sum = 0.f;
#pragma unroll
    for (int i = 0; i < 16; i++) { r[i] = __expf(r[i] - smax); sum += r[i]; }
    const float inv = 1.f / block_red<false>(sum, red, t);

    float mx2 = -INFINITY;
    if (mrowf) {
#pragma unroll
        for (int c = 0; c < 2; c++)
#pragma unroll
            for (int h = 0; h < 2; h++) {
                float4 mm = *(const float4*)(mrowf + c * 2048 + t * 8 + h * 4);
                float* rr = &r[c*8 + h*4];
                rr[0] = rr[0] * inv * ((mm.x != 0.f) ? 1.f : 0.f);
                rr[1] = rr[1] * inv * ((mm.y != 0.f) ? 1.f : 0.f);
                rr[2] = rr[2] * inv * ((mm.z != 0.f) ? 1.f : 0.f);
                rr[3] = rr[3] * inv * ((mm.w != 0.f) ? 1.f : 0.f);
                mx2 = fmaxf(mx2, fmaxf(fmaxf(rr[0], rr[1]), fmaxf(rr[2], rr[3])));
            }
    } else {
#pragma unroll
        for (int c = 0; c < 2; c++) {
            uint2 mb = *(const uint2*)(mrowb + c * 2048 + t * 8);
#pragma unroll
            for (int b = 0; b < 4; b++) {
                float m0 = (float)((mb.x >> (8*b)) & 0xFF);
                float m1 = (float)((mb.y >> (8*b)) & 0xFF);
                r[c*8 + b]     = r[c*8 + b]     * inv * m0;
                r[c*8 + 4 + b] = r[c*8 + 4 + b] * inv * m1;
                mx2 = fmaxf(mx2, fmaxf(r[c*8 + b], r[c*8 + 4 + b]));
            }
        }
    }
    const float smax2 = block_red<true>(mx2, red, t);

    float sum2 = 0.f;
#pragma unroll
    for (int i = 0; i < 16; i++) { r[i] = __expf(r[i] - smax2); sum2 += r[i]; }
    const float inv2 = 1.f / block_red<false>(sum2, red, t);

#pragma unroll
    for (int c = 0; c < 2; c++) {
        uint4 raw;
        __half2* h2 = (__half2*)&raw;
#pragma unroll
        for (int q = 0; q < 4; q++) {
            h2[q].x = __float2half_rn(r[c*8 + 2*q]     * inv2);
            h2[q].y = __float2half_rn(r[c*8 + 2*q + 1] * inv2);
        }
        __stcg((uint4*)(Srow + c * 2048 + t * 8), raw);
    }
}

// ============================================================================
// persistent dataflow mega-kernel
// ============================================================================
__global__ void __launch_bounds__(256, 2) mega_kernel(
    const __half* __restrict__ Hh, const __half* __restrict__ HT,
    __half* __restrict__ Sh, __half* __restrict__ H4,
    const __half* __restrict__ Wh,
    const float* __restrict__ Lm, const unsigned char* __restrict__ MT,
    const float* __restrict__ Bh, const float* __restrict__ bias,
    float* __restrict__ out)
{
    __shared__ __align__(128) char sm[NST * STB];   // 48 KB exactly
    const int t = threadIdx.x;
    // scratch lives in stage-2 region: untouched during the windows it's used
    float* red = (float*)(sm + 2 * STB);
    unsigned* s_tk = (unsigned*)(sm + 2 * STB + 128);
    const float scale = 0.03125f;

    // phase A: score tiles
    for (;;) {
        __syncthreads();
        if (t == 0) *s_tk = atomicAdd(&g_tickA, 1u);
        __syncthreads();
        const unsigned tk = *s_tk;
        __syncthreads();
        if (tk >= 3072u) break;
        const int z = tk / 1024u, rem = tk % 1024u, my = rem / 32, nx = rem % 32;
        gemm_tile<0, 128>(sm, t, Hh, DDIM, Hh + (size_t)z * HSZ, DDIM, DDIM,
                          scale, Sh + (size_t)z * NN, nullptr, NDIM, nullptr,
                          my * 128, nx * 128);
        __threadfence();
        __syncthreads();
        if (t == 0) atomicAdd(&g_cntS[z * 32 + my], 1u);
    }

    // phase B: softmax chunks (gated on scores of (z,my))
    for (;;) {
        __syncthreads();
        if (t == 0) *s_tk = atomicAdd(&g_tickB, 1u);
        __syncthreads();
        const unsigned tk = *s_tk;
        __syncthreads();
        if (tk >= 1536u) break;
        const int b = tk >> 4, z = b / 32, my = b % 32, ch = tk & 15;
        if (t == 0) { while (atomicAdd(&g_cntS[b], 0u) < 32u) __nanosleep(128); }
        __syncthreads();
        const int row0 = my * 128 + ch * 8;
        for (int rr = 0; rr < 8; rr++) {
            const size_t row = row0 + rr;
            __half* Srow = Sh + (size_t)z * NN + row * NDIM;
            const float* mf = (z == 0) ? (Lm + row * NDIM)
                            : (z == 2) ? (Bh + row * NDIM) : nullptr;
            const unsigned char* mb = (z == 1) ? (MT + row * NDIM) : nullptr;
            softmax_row(Srow, mf, mb, t, red);
        }
        __threadfence();
        __syncthreads();
        if (t == 0) atomicAdd(&g_cntP[b], 1u);
    }

    // phase C: AV tiles (gated on softmax of (z,my))
    for (;;) {
        __syncthreads();
        if (t == 0) *s_tk = atomicAdd(&g_tickC, 1u);
        __syncthreads();
        const unsigned tk = *s_tk;
        __syncthreads();
        if (tk >= 768u) break;
        const int z = tk / 256u, rem = tk % 256u, my = rem / 8, nx = rem % 8;
        if (t == 0) { while (atomicAdd(&g_cntP[z * 32 + my], 0u) < 16u) __nanosleep(128); }
        __syncthreads();
        gemm_tile<1, 128>(sm, t, Sh + (size_t)z * NN, NDIM, HT + (size_t)z * HSZ, NDIM, NDIM,
                          1.f, H4 + z * DDIM, nullptr, 3 * DDIM, nullptr,
                          my * 128, nx * 128);
        __threadfence();
        __syncthreads();
        if (t == 0) atomicAdd(&g_cntH[my], 1u);
    }

    // phase D: final tiles 128x64 (gated on H4 rows of my)
    for (;;) {
        __syncthreads();
        if (t == 0) *s_tk = atomicAdd(&g_tickD, 1u);
        __syncthreads();
        const unsigned tk = *s_tk;
        __syncthreads();
        if (tk >= 512u) break;
        const int my = tk >> 4, nx = tk & 15;
        if (t == 0) { while (atomicAdd(&g_cntH[my], 0u) < 24u) __nanosleep(128); }
        __syncthreads();
        gemm_tile<2, 64>(sm, t, H4, 3 * DDIM, Wh, 3 * DDIM, 3 * DDIM,
                         1.f, nullptr, out, DDIM, bias, my * 128, nx * 64);
    }

    // reset state for next replay (last CTA out)
    __syncthreads();
    if (t == 0) {
        const unsigned d = atomicAdd(&g_done, 1u);
        if (d == gridDim.x - 1) {
            g_tickA = 0u; g_tickB = 0u; g_tickC = 0u; g_tickD = 0u;
            for (int i = 0; i < 96; i++) { g_cntS[i] = 0u; g_cntP[i] = 0u; }
            for (int i = 0; i < 32; i++) g_cntH[i] = 0u;
            __threadfence();
            g_done = 0u;
        }
    }
}

// ---------------- prep kernels ----------------
__global__ void roundH_kernel(const float* __restrict__ X0,
                              const float* __restrict__ X1,
                              const float* __restrict__ X2,
                              __half* __restrict__ Y, int per)
{
    const int zz = blockIdx.y;
    const float* X = (zz == 0) ? X0 : (zz == 1) ? X1 : X2;
    __half* Yz = Y + (size_t)zz * per;
    int i = (blockIdx.x * blockDim.x + threadIdx.x) * 4;
    if (i >= per) return;
    float4 v = *(const float4*)(X + i);
    __half2 a; a.x = __float2half_rn(v.x); a.y = __float2half_rn(v.y);
    __half2 b; b.x = __float2half_rn(v.z); b.y = __float2half_rn(v.w);
    *(__half2*)(Yz + i)     = a;
    *(__half2*)(Yz + i + 2) = b;
}

__global__ void round_kernel(const float* __restrict__ X,
                             __half* __restrict__ hi, int count)
{
    int i = (blockIdx.x * blockDim.x + threadIdx.x) * 4;
    if (i >= count) return;
    float4 v = *(const float4*)(X + i);
    __half2 a; a.x = __float2half_rn(v.x); a.y = __float2half_rn(v.y);
    __half2 b; b.x = __float2half_rn(v.z); b.y = __float2half_rn(v.w);
    *(__half2*)(hi + i)     = a;
    *(__half2*)(hi + i + 2) = b;
}

__global__ void round_t3_kernel(const float* __restrict__ X0,
                                const float* __restrict__ X1,
                                const float* __restrict__ X2,
                                __half* __restrict__ hT, int R, int C)
{
    __shared__ float tile[32][33];
    const int zz = blockIdx.z;
    const float* X = (zz == 0) ? X0 : (zz == 1) ? X1 : X2;
    __half* o = hT + (size_t)zz * R * C;
    const int c0 = blockIdx.x * 32;
    const int r0 = blockIdx.y * 32;
    const int tx = threadIdx.x;
    const int ty = threadIdx.y;
#pragma unroll
    for (int j = ty; j < 32; j += 8)
        tile[j][tx] = X[(size_t)(r0 + j) * C + c0 + tx];
    __syncthreads();
#pragma unroll
    for (int j = ty; j < 32; j += 8)
        o[(size_t)(c0 + j) * R + r0 + tx] = __float2half_rn(tile[tx][j]);
}

__global__ void mask_transpose_kernel(const float* __restrict__ B,
                                      unsigned char* __restrict__ MT)
{
    __shared__ unsigned char tile[32][33];
    const int bx = blockIdx.x * 32;
    const int by = blockIdx.y * 32;
    const int tx = threadIdx.x;
    const int ty = threadIdx.y;
#pragma unroll
    for (int j = ty; j < 32; j += 8)
        tile[j][tx] = (B[(size_t)(by + j) * NDIM + bx + tx] != 0.f) ? 1 : 0;
    __syncthreads();
#pragma unroll
    for (int j = ty; j < 32; j += 8)
        MT[(size_t)(bx + j) * NDIM + by + tx] = tile[tx][j];
}

// ---------------- launch (single stream, no streams/events) ----------------
extern "C" void kernel_launch(void* const* d_in, const int* in_sizes, int n_in,
                              void* d_out, int out_size)
{
    const float* L      = (const float*)d_in[0];
    const float* H      = (const float*)d_in[1];
    const float* B_low  = (const float*)d_in[2];
    const float* H_low  = (const float*)d_in[3];
    const float* B_high = (const float*)d_in[4];
    const float* H_high = (const float*)d_in[5];
    const float* W      = (const float*)d_in[6];
    const float* bvec   = (const float*)d_in[7];
    float* out = (float*)d_out;

    __half *Sh, *Hh, *HT, *H4, *Wh;
    unsigned char* MT;
    cudaGetSymbolAddress((void**)&Sh, g_Sh);
    cudaGetSymbolAddress((void**)&Hh, g_Hh);
    cudaGetSymbolAddress((void**)&HT, g_HT);
    cudaGetSymbolAddress((void**)&H4, g_H4);
    cudaGetSymbolAddress((void**)&Wh, g_Wh);
    cudaGetSymbolAddress((void**)&MT, g_MT);

    const int rt = 256;
    roundH_kernel<<<dim3((unsigned)(HSZ / 4 / rt), 3), rt>>>(H, H_low, H_high, Hh, (int)HSZ);
    round_kernel<<<(int)((size_t)DDIM * 3 * DDIM / 4 / rt), rt>>>(
        W, Wh, (int)((size_t)DDIM * 3 * DDIM));
    round_t3_kernel<<<dim3(DDIM / 32, NDIM / 32, 3), dim3(32, 8)>>>(
        H, H_low, H_high, HT, NDIM, DDIM);
    mask_transpose_kernel<<<dim3(NDIM / 32, NDIM / 32), dim3(32, 8)>>>(B_low, MT);

    mega_kernel<<<296, 256>>>(Hh, HT, Sh, H4, Wh, L, MT, B_high, bvec, out);
}